// round 3
// baseline (speedup 1.0000x reference)
#include <cuda_runtime.h>
#include <cstdint>

#define VOCAB 32000
#define BOS_ID 1
#define BSZ 8
#define SEQLEN 2048

// ---------------------------------------------------------------------------
// Kernel 1: pure -6.0f broadcast. Zero data dependency, zero index math beyond
// the base offset. Each thread issues 8 coalesced STG.128; block covers 128KB.
// Total floats = BSZ*SEQLEN*VOCAB = 524,288,000 = 131,072,000 float4.
// 131,072,000 / 2048 float4-per-block = 64000 blocks.
// ---------------------------------------------------------------------------
__global__ void __launch_bounds__(256) fill_kernel(float4* __restrict__ out) {
    const float4 v = make_float4(-6.0f, -6.0f, -6.0f, -6.0f);
    float4* p = out + (long long)blockIdx.x * 2048 + threadIdx.x;
    #pragma unroll
    for (int j = 0; j < 8; j++) {
        p[j * 256] = v;
    }
}

// ---------------------------------------------------------------------------
// Kernel 2 (after fill): per-row histogram + argmax (ties -> lowest index,
// BOS fallback), then patch +6.0f at (b, s, pred) for all s.
// One block per batch row; dynamic smem = VOCAB ints (128000 B, opt-in).
// ---------------------------------------------------------------------------
__global__ void hist_patch_kernel(const int* __restrict__ ids,
                                  float* __restrict__ out) {
    extern __shared__ int counts[];
    __shared__ int sh_best;

    const int b = blockIdx.x;
    const int t = threadIdx.x;
    const int nt = blockDim.x;

    for (int i = t; i < VOCAB; i += nt) counts[i] = 0;
    if (t == 0) sh_best = 0;
    __syncthreads();

    const int* row = ids + b * SEQLEN;
    #pragma unroll 2
    for (int i = t; i < SEQLEN; i += nt) {
        int v = row[i];
        if (v != 0 && v != BOS_ID) atomicAdd(&counts[v], 1);
    }
    __syncthreads();

    // Packed key: (count << 15) | (0x7FFF - v).
    // Higher count wins; equal count -> lower v wins (argmax tie rule).
    // count <= 2048 (12 bits), v < 32000 (15 bits) -> packed < 2^27, no overflow.
    int best = 0;
    for (int i = t; i < VOCAB; i += nt) {
        int packed = (counts[i] << 15) | (0x7FFF - i);
        if (packed > best) best = packed;
    }
    atomicMax(&sh_best, best);
    __syncthreads();

    const int cnt  = sh_best >> 15;
    const int pred = (cnt > 0) ? (0x7FFF - (sh_best & 0x7FFF)) : BOS_ID;

    // Patch: out[b][s][pred] = +6 for every s. 2048 scattered 4B stores/block.
    float* base = out + (long long)b * SEQLEN * VOCAB + pred;
    for (int s = t; s < SEQLEN; s += nt) {
        base[(long long)s * VOCAB] = 6.0f;
    }
}

// ---------------------------------------------------------------------------
extern "C" void kernel_launch(void* const* d_in, const int* in_sizes, int n_in,
                              void* d_out, int out_size) {
    (void)in_sizes; (void)n_in; (void)out_size;
    const int* ids = (const int*)d_in[0];

    const int smem_bytes = VOCAB * (int)sizeof(int);  // 128000 bytes
    cudaFuncSetAttribute(hist_patch_kernel,
                         cudaFuncAttributeMaxDynamicSharedMemorySize, smem_bytes);

    // 131,072,000 float4 total / 2048 per block = 64000 blocks
    fill_kernel<<<64000, 256>>>((float4*)d_out);
    hist_patch_kernel<<<BSZ, 1024, smem_bytes>>>(ids, (float*)d_out);
}

// round 4
// speedup vs baseline: 1.0226x; 1.0226x over previous
#include <cuda_runtime.h>
#include <cstdint>

#define VOCAB 32000
#define BOS_ID 1
#define BSZ 8
#define SEQLEN 2048

// Per-row majority token, computed by hist_kernel, consumed by fill_kernel.
__device__ int g_pred[BSZ];

// ---------------------------------------------------------------------------
// Kernel 1: per-row histogram + argmax (ties -> lowest index), BOS fallback.
// One block per batch row. Dynamic smem: VOCAB ints = 128000 bytes (opt-in).
// Vectorized init/scan (int4), REDUX warp reductions -> minimal latency.
// ---------------------------------------------------------------------------
__global__ void __launch_bounds__(1024) hist_kernel(const int* __restrict__ ids) {
    extern __shared__ int counts[];
    __shared__ int warp_best[32];

    const int b = blockIdx.x;
    const int t = threadIdx.x;

    int4* c4 = (int4*)counts;               // VOCAB/4 = 8000 int4
    #pragma unroll
    for (int i = t; i < VOCAB / 4; i += 1024) c4[i] = make_int4(0, 0, 0, 0);
    __syncthreads();

    const int* row = ids + b * SEQLEN;
    #pragma unroll
    for (int i = t; i < SEQLEN; i += 1024) {
        int v = row[i];
        if (v > BOS_ID) atomicAdd(&counts[v], 1);  // valid <=> v!=0 && v!=1 <=> v>1
    }
    __syncthreads();

    // Packed key: (count << 15) | (0x7FFF - v).
    // Higher count wins; equal count -> lower v wins (argmax tie rule).
    // count <= 2048 (12 bits), v < 32000 (15 bits) -> packed < 2^27.
    int best = 0;
    #pragma unroll
    for (int i = t; i < VOCAB / 4; i += 1024) {
        int4 c = c4[i];
        int vb = 0x7FFF - 4 * i;
        best = max(best, (c.x << 15) | vb);
        best = max(best, (c.y << 15) | (vb - 1));
        best = max(best, (c.z << 15) | (vb - 2));
        best = max(best, (c.w << 15) | (vb - 3));
    }
    best = __reduce_max_sync(0xFFFFFFFFu, best);
    if ((t & 31) == 0) warp_best[t >> 5] = best;
    __syncthreads();

    if (t < 32) {
        best = __reduce_max_sync(0xFFFFFFFFu, warp_best[t]);
        if (t == 0) {
            int cnt = best >> 15;
            g_pred[b] = (cnt > 0) ? (0x7FFF - (best & 0x7FFF)) : BOS_ID;
        }
    }
}

// ---------------------------------------------------------------------------
// Kernel 2: stream 2.1 GB of logits. One float4 (STG.128) per thread.
// grid = (SEQLEN*VOCAB/4/256, BSZ). Proven at 95.4% DRAM (269.4us) in R1.
// ---------------------------------------------------------------------------
__global__ void __launch_bounds__(256) fill_kernel(float4* __restrict__ out) {
    const int ROW4 = VOCAB / 4;                       // 8000 float4 per (b,s) row
    const long long per_b = (long long)SEQLEN * ROW4; // 16,384,000 float4 per batch

    const int b = blockIdx.y;
    const long long i_in_b = (long long)blockIdx.x * blockDim.x + threadIdx.x;
    const int r = (int)(i_in_b % ROW4);               // float4 index within vocab row

    const int pred = g_pred[b];

    float4 val = make_float4(-6.0f, -6.0f, -6.0f, -6.0f);
    const int vb = r * 4;
    if (pred >= vb && pred < vb + 4) {
        reinterpret_cast<float*>(&val)[pred - vb] = 6.0f;
    }

    out[(long long)b * per_b + i_in_b] = val;
}

// ---------------------------------------------------------------------------
extern "C" void kernel_launch(void* const* d_in, const int* in_sizes, int n_in,
                              void* d_out, int out_size) {
    (void)in_sizes; (void)n_in; (void)out_size;
    const int* ids = (const int*)d_in[0];
    float4* out = (float4*)d_out;

    const int smem_bytes = VOCAB * (int)sizeof(int);  // 128000 bytes
    cudaFuncSetAttribute(hist_kernel,
                         cudaFuncAttributeMaxDynamicSharedMemorySize, smem_bytes);

    hist_kernel<<<BSZ, 1024, smem_bytes>>>(ids);

    // SEQLEN * VOCAB/4 = 16,384,000 float4 per batch row; / 256 threads = 64000 blocks
    dim3 grid((SEQLEN * (VOCAB / 4)) / 256, BSZ);
    fill_kernel<<<grid, 256>>>(out);
}

// round 5
// speedup vs baseline: 1.0230x; 1.0003x over previous
#include <cuda_runtime.h>
#include <cstdint>

#define VOCAB 32000
#define BOS_ID 1
#define BSZ 8
#define SEQLEN 2048

// Per-row majority token, computed by hist_kernel, consumed by fill_kernel.
__device__ int g_pred[BSZ];

// ---------------------------------------------------------------------------
// Kernel 1: per-row histogram + argmax (ties -> lowest index), BOS fallback.
// One block per batch row. Dynamic smem: VOCAB ints = 128000 bytes (opt-in).
// Triggers programmatic launch completion at entry so the dependent fill
// grid can begin launching while this runs.
// ---------------------------------------------------------------------------
__global__ void __launch_bounds__(1024) hist_kernel(const int* __restrict__ ids) {
    cudaTriggerProgrammaticLaunchCompletion();

    extern __shared__ int counts[];
    __shared__ int warp_best[32];

    const int b = blockIdx.x;
    const int t = threadIdx.x;

    int4* c4 = (int4*)counts;               // VOCAB/4 = 8000 int4
    #pragma unroll
    for (int i = t; i < VOCAB / 4; i += 1024) c4[i] = make_int4(0, 0, 0, 0);
    __syncthreads();

    const int* row = ids + b * SEQLEN;
    #pragma unroll
    for (int i = t; i < SEQLEN; i += 1024) {
        int v = row[i];
        if (v > BOS_ID) atomicAdd(&counts[v], 1);  // valid <=> v!=0 && v!=1 <=> v>1
    }
    __syncthreads();

    // Packed key: (count << 15) | (0x7FFF - v).
    // Higher count wins; equal count -> lower v wins (argmax tie rule).
    // count <= 2048 (12 bits), v < 32000 (15 bits) -> packed < 2^27.
    int best = 0;
    #pragma unroll
    for (int i = t; i < VOCAB / 4; i += 1024) {
        int4 c = c4[i];
        int vb = 0x7FFF - 4 * i;
        best = max(best, (c.x << 15) | vb);
        best = max(best, (c.y << 15) | (vb - 1));
        best = max(best, (c.z << 15) | (vb - 2));
        best = max(best, (c.w << 15) | (vb - 3));
    }
    best = __reduce_max_sync(0xFFFFFFFFu, best);
    if ((t & 31) == 0) warp_best[t >> 5] = best;
    __syncthreads();

    if (t < 32) {
        best = __reduce_max_sync(0xFFFFFFFFu, warp_best[t]);
        if (t == 0) {
            int cnt = best >> 15;
            g_pred[b] = (cnt > 0) ? (0x7FFF - (best & 0x7FFF)) : BOS_ID;
        }
    }
}

// ---------------------------------------------------------------------------
// Kernel 2: stream 2.1 GB of logits. One float4 (STG.128) per thread.
// grid = (64000, 8). Proven at 95% DRAM (269-270us). Launched with PDL;
// waits for hist's memory before reading g_pred.
// ---------------------------------------------------------------------------
__global__ void __launch_bounds__(256) fill_kernel(float4* __restrict__ out) {
    cudaGridDependencySynchronize();

    const int ROW4 = VOCAB / 4;                       // 8000 float4 per (b,s) row
    const long long per_b = (long long)SEQLEN * ROW4; // 16,384,000 float4 per batch

    const int b = blockIdx.y;
    const long long i_in_b = (long long)blockIdx.x * blockDim.x + threadIdx.x;
    const int r = (int)(i_in_b % ROW4);               // float4 index within vocab row

    const int pred = g_pred[b];

    float4 val = make_float4(-6.0f, -6.0f, -6.0f, -6.0f);
    const int vb = r * 4;
    if (pred >= vb && pred < vb + 4) {
        reinterpret_cast<float*>(&val)[pred - vb] = 6.0f;
    }

    out[(long long)b * per_b + i_in_b] = val;
}

// ---------------------------------------------------------------------------
extern "C" void kernel_launch(void* const* d_in, const int* in_sizes, int n_in,
                              void* d_out, int out_size) {
    (void)in_sizes; (void)n_in; (void)out_size;
    const int* ids = (const int*)d_in[0];
    float4* out = (float4*)d_out;

    const int smem_bytes = VOCAB * (int)sizeof(int);  // 128000 bytes
    cudaFuncSetAttribute(hist_kernel,
                         cudaFuncAttributeMaxDynamicSharedMemorySize, smem_bytes);

    hist_kernel<<<BSZ, 1024, smem_bytes>>>(ids);

    // Fill launched with programmatic stream serialization (PDL): it may begin
    // launching once hist triggers; griddepsync inside guards the g_pred read.
    cudaLaunchConfig_t cfg = {};
    cfg.gridDim = dim3((SEQLEN * (VOCAB / 4)) / 256, BSZ);  // (64000, 8)
    cfg.blockDim = dim3(256);
    cfg.dynamicSmemBytes = 0;
    cfg.stream = 0;
    cudaLaunchAttribute attrs[1];
    attrs[0].id = cudaLaunchAttributeProgrammaticStreamSerialization;
    attrs[0].val.programmaticStreamSerializationAllowed = 1;
    cfg.attrs = attrs;
    cfg.numAttrs = 1;
    cudaLaunchKernelEx(&cfg, fill_kernel, out);
}